// round 1
// baseline (speedup 1.0000x reference)
#include <cuda_runtime.h>
#include <math.h>

// ---------------------------------------------------------------------------
// Problem constants: x (1,512,32,32); all spatial = 32x32 = 1024 px.
// ---------------------------------------------------------------------------
static constexpr long O_FEAS   = 0;            // 3 * 524288
static constexpr long O_BMEAN  = 1572864;      // 1536
static constexpr long O_ATT    = 1574400;      // 1536
static constexpr long O_OUTRES = 1575936;      // 524288  (skconv output = out_res)
static constexpr long O_FDT    = 2100224;      // 131072  fd^T [s][c] 256x512
static constexpr long O_G      = 2231296;      // 65536   gram 256x256
static constexpr long O_NRM    = 2296832;      // 256
static constexpr long O_YIS    = 2297088;      // 65536   softmaxed yi [p][s]
static constexpr long O_WK     = 2362624;      // 2097152 Wk[16][512][256]
static constexpr long O_TB     = 4459776;      // 2097152 T[16][512][256]
static constexpr long O_RALOUT = 6556928;      // 524288  ral output [c][hw]
static constexpr long O_RALT   = 7081216;      // 524288  ral output [hw][c]
static constexpr long O_SIGT   = 7605504;      // 524288  sigmoid(ral) [hw][c]
static constexpr long O_GUSB   = 8129792;      // 524288  gus result [p][c] flat
static constexpr long O_CSAB   = 8654080;      // 524288  csa result [p][c] flat
static constexpr long O_Y1RAW  = 9178368;      // 524288
static constexpr long O_Y1     = 9702656;      // 524288
static constexpr long O_Y2RAW  = 10226944;     // 524288
static constexpr long SCRATCH  = 10751232;

__device__ __align__(256) float g_scratch[SCRATCH];

// ---------------------------------------------------------------------------
// Block reductions (blockDim.x == 256)
// ---------------------------------------------------------------------------
__device__ __forceinline__ float blockReduceSum(float v, float* red) {
    int t = threadIdx.x;
    red[t] = v; __syncthreads();
    #pragma unroll
    for (int s = 128; s > 0; s >>= 1) {
        if (t < s) red[t] += red[t + s];
        __syncthreads();
    }
    float r = red[0]; __syncthreads();
    return r;
}
__device__ __forceinline__ float blockReduceMax(float v, float* red) {
    int t = threadIdx.x;
    red[t] = v; __syncthreads();
    #pragma unroll
    for (int s = 128; s > 0; s >>= 1) {
        if (t < s) red[t] = fmaxf(red[t], red[t + s]);
        __syncthreads();
    }
    float r = red[0]; __syncthreads();
    return r;
}

// ---------------------------------------------------------------------------
// 1) Grouped conv (16 in-ch per group) + instance norm + ReLU + channel mean.
//    One block per output channel. Bias is dead (cancelled by inorm).
// ---------------------------------------------------------------------------
template <int KW>
__global__ __launch_bounds__(256) void k_skconv(
    const float* __restrict__ x, const float* __restrict__ w,
    float* __restrict__ fea, float* __restrict__ bmean)
{
    constexpr int PAD  = (KW - 1) / 2;
    constexpr int S    = 32 + 2 * PAD;
    constexpr int TAPS = KW * KW;
    extern __shared__ float sm[];
    float* wsm = sm;              // 16*TAPS
    float* xt  = sm + 16 * TAPS;  // S*S
    __shared__ float red[256];

    const int c = blockIdx.x;
    const int t = threadIdx.x;
    const int g = c >> 4;
    const int px0 = t & 31, py0 = t >> 5;

    for (int i = t; i < 16 * TAPS; i += 256) wsm[i] = w[c * 16 * TAPS + i];

    float acc[4] = {0.f, 0.f, 0.f, 0.f};
    for (int ci = 0; ci < 16; ci++) {
        __syncthreads();
        const float* xc = x + (g * 16 + ci) * 1024;
        for (int i = t; i < S * S; i += 256) {
            int r  = i / S - PAD;
            int cc = i % S - PAD;
            xt[i] = (r >= 0 && r < 32 && cc >= 0 && cc < 32) ? xc[r * 32 + cc] : 0.f;
        }
        __syncthreads();
        const float* wc = wsm + ci * TAPS;
        #pragma unroll
        for (int q = 0; q < 4; q++) {
            const float* xb = xt + (py0 + q * 8) * S + px0;
            float a = acc[q];
            #pragma unroll
            for (int ky = 0; ky < KW; ky++) {
                const float* xr = xb + ky * S;
                const float* wr = wc + ky * KW;
                #pragma unroll
                for (int kx = 0; kx < KW; kx++) a += wr[kx] * xr[kx];
            }
            acc[q] = a;
        }
    }
    // instance norm over 1024 pixels
    float s  = acc[0] + acc[1] + acc[2] + acc[3];
    float sq = acc[0]*acc[0] + acc[1]*acc[1] + acc[2]*acc[2] + acc[3]*acc[3];
    s  = blockReduceSum(s,  red);
    sq = blockReduceSum(sq, red);
    float mean = s * (1.f / 1024.f);
    float var  = sq * (1.f / 1024.f) - mean * mean;
    float rstd = rsqrtf(var + 1e-5f);
    float rsum = 0.f;
    #pragma unroll
    for (int q = 0; q < 4; q++) {
        float v = (acc[q] - mean) * rstd;
        v = fmaxf(v, 0.f);
        fea[c * 1024 + (py0 + q * 8) * 32 + px0] = v;
        rsum += v;
    }
    rsum = blockReduceSum(rsum, red);
    if (t == 0) bmean[c] = rsum * (1.f / 1024.f);
}

// ---------------------------------------------------------------------------
// 2) SK attention: fea_s -> fc -> per-channel 3-way softmax. 1 block x 512thr
// ---------------------------------------------------------------------------
__global__ __launch_bounds__(512) void k_att(
    const float* __restrict__ bmean, const float* __restrict__ fc_w,
    const float* __restrict__ fc_b,  const float* __restrict__ fcs_w,
    const float* __restrict__ fcs_b, float* __restrict__ att)
{
    __shared__ float sfeas[512];
    __shared__ float sz[32];
    int t = threadIdx.x;
    sfeas[t] = bmean[t] + bmean[512 + t] + bmean[1024 + t];
    __syncthreads();
    int w = t >> 5, lane = t & 31;
    for (int d = w; d < 32; d += 16) {
        float a = 0.f;
        for (int c = lane; c < 512; c += 32) a += sfeas[c] * fc_w[d * 512 + c];
        #pragma unroll
        for (int off = 16; off; off >>= 1) a += __shfl_down_sync(0xffffffffu, a, off);
        if (lane == 0) sz[d] = a + fc_b[d];
    }
    __syncthreads();
    int c = t;
    float av[3];
    #pragma unroll
    for (int m = 0; m < 3; m++) {
        float a = fcs_b[m * 512 + c];
        const float* fw = fcs_w + (m * 512 + c) * 32;
        #pragma unroll
        for (int d = 0; d < 32; d++) a += sz[d] * fw[d];
        av[m] = a;
    }
    float mx = fmaxf(av[0], fmaxf(av[1], av[2]));
    float e0 = expf(av[0] - mx), e1 = expf(av[1] - mx), e2 = expf(av[2] - mx);
    float inv = 1.f / (e0 + e1 + e2);
    att[c] = e0 * inv; att[512 + c] = e1 * inv; att[1024 + c] = e2 * inv;
}

// 3) mix: out_res = sum_m att[m,c]*feas[m]
__global__ __launch_bounds__(256) void k_mix(const float* __restrict__ feas,
                                             const float* __restrict__ att,
                                             float* __restrict__ outres)
{
    int idx = blockIdx.x * 256 + threadIdx.x;
    int c = idx >> 10;
    outres[idx] = att[c] * feas[idx] + att[512 + c] * feas[524288 + idx]
                + att[1024 + c] * feas[1048576 + idx];
}

// 4) downsample-transpose: fdT[s][c] = out_res[c, 2sy, 2sx]
__global__ __launch_bounds__(256) void k_fd(const float* __restrict__ outres,
                                            float* __restrict__ fdT)
{
    int idx = blockIdx.x * 256 + threadIdx.x;  // 131072
    int c = idx & 511, s = idx >> 9;
    fdT[idx] = outres[c * 1024 + (s >> 4) * 64 + (s & 15) * 2];
}

// ---------------------------------------------------------------------------
// Tiled SGEMM variants. 64x64 tile, BK=16, 256 threads, 4x4 microtile.
// gemm_ab : C[m][n] = sum_k A[m*K+k] * B[k*N+n]   (B split at K1 into B1/B2)
// gemm_abt: C[m][n] = sum_k A[m*K+k] * B[n*K+k]
// Grid: (N/64, M/64, batch)
// ---------------------------------------------------------------------------
__global__ __launch_bounds__(256) void gemm_ab(
    const float* __restrict__ A, const float* __restrict__ B1,
    const float* __restrict__ B2, int K1, float* __restrict__ C,
    int M, int N, int K, long sA, long sB, long sC)
{
    A  += (long)blockIdx.z * sA;
    B1 += (long)blockIdx.z * sB;
    B2 += (long)blockIdx.z * sB;
    C  += (long)blockIdx.z * sC;
    __shared__ float As[16][68];
    __shared__ float Bs[16][68];
    int tid = threadIdx.x;
    int tx = tid & 15, ty = tid >> 4;
    int m0 = blockIdx.y * 64, n0 = blockIdx.x * 64;
    int a_m = tid >> 2, a_k4 = (tid & 3) * 4;
    int b_k = tid >> 4, b_n4 = (tid & 15) * 4;
    float acc[4][4] = {};
    for (int kt = 0; kt < K; kt += 16) {
        float4 av = *(const float4*)(A + (long)(m0 + a_m) * K + kt + a_k4);
        As[a_k4 + 0][a_m] = av.x; As[a_k4 + 1][a_m] = av.y;
        As[a_k4 + 2][a_m] = av.z; As[a_k4 + 3][a_m] = av.w;
        int gk = kt + b_k;
        const float* src = (gk < K1) ? (B1 + (long)gk * N) : (B2 + (long)(gk - K1) * N);
        *(float4*)&Bs[b_k][b_n4] = *(const float4*)(src + n0 + b_n4);
        __syncthreads();
        #pragma unroll
        for (int kk = 0; kk < 16; kk++) {
            float4 a = *(const float4*)&As[kk][ty * 4];
            float4 b = *(const float4*)&Bs[kk][tx * 4];
            acc[0][0] += a.x * b.x; acc[0][1] += a.x * b.y; acc[0][2] += a.x * b.z; acc[0][3] += a.x * b.w;
            acc[1][0] += a.y * b.x; acc[1][1] += a.y * b.y; acc[1][2] += a.y * b.z; acc[1][3] += a.y * b.w;
            acc[2][0] += a.z * b.x; acc[2][1] += a.z * b.y; acc[2][2] += a.z * b.z; acc[2][3] += a.z * b.w;
            acc[3][0] += a.w * b.x; acc[3][1] += a.w * b.y; acc[3][2] += a.w * b.z; acc[3][3] += a.w * b.w;
        }
        __syncthreads();
    }
    #pragma unroll
    for (int i = 0; i < 4; i++) {
        float4 v = make_float4(acc[i][0], acc[i][1], acc[i][2], acc[i][3]);
        *(float4*)(C + (long)(m0 + ty * 4 + i) * N + n0 + tx * 4) = v;
    }
}

__global__ __launch_bounds__(256) void gemm_abt(
    const float* __restrict__ A, const float* __restrict__ B,
    float* __restrict__ C, int M, int N, int K)
{
    __shared__ float As[16][68];
    __shared__ float Bs[16][68];
    int tid = threadIdx.x;
    int tx = tid & 15, ty = tid >> 4;
    int m0 = blockIdx.y * 64, n0 = blockIdx.x * 64;
    int a_m = tid >> 2, a_k4 = (tid & 3) * 4;
    float acc[4][4] = {};
    for (int kt = 0; kt < K; kt += 16) {
        float4 av = *(const float4*)(A + (long)(m0 + a_m) * K + kt + a_k4);
        As[a_k4 + 0][a_m] = av.x; As[a_k4 + 1][a_m] = av.y;
        As[a_k4 + 2][a_m] = av.z; As[a_k4 + 3][a_m] = av.w;
        float4 bv = *(const float4*)(B + (long)(n0 + a_m) * K + kt + a_k4);
        Bs[a_k4 + 0][a_m] = bv.x; Bs[a_k4 + 1][a_m] = bv.y;
        Bs[a_k4 + 2][a_m] = bv.z; Bs[a_k4 + 3][a_m] = bv.w;
        __syncthreads();
        #pragma unroll
        for (int kk = 0; kk < 16; kk++) {
            float4 a = *(const float4*)&As[kk][ty * 4];
            float4 b = *(const float4*)&Bs[kk][tx * 4];
            acc[0][0] += a.x * b.x; acc[0][1] += a.x * b.y; acc[0][2] += a.x * b.z; acc[0][3] += a.x * b.w;
            acc[1][0] += a.y * b.x; acc[1][1] += a.y * b.y; acc[1][2] += a.y * b.z; acc[1][3] += a.y * b.w;
            acc[2][0] += a.z * b.x; acc[2][1] += a.z * b.y; acc[2][2] += a.z * b.z; acc[2][3] += a.z * b.w;
            acc[3][0] += a.w * b.x; acc[3][1] += a.w * b.y; acc[3][2] += a.w * b.z; acc[3][3] += a.w * b.w;
        }
        __syncthreads();
    }
    #pragma unroll
    for (int i = 0; i < 4; i++) {
        float4 v = make_float4(acc[i][0], acc[i][1], acc[i][2], acc[i][3]);
        *(float4*)(C + (long)(m0 + ty * 4 + i) * N + n0 + tx * 4) = v;
    }
}

// 5) patch norms from gram diagonal: nrm[p] = max(sqrt(sum valid diag),1e-4)
__global__ __launch_bounds__(256) void k_nrm(const float* __restrict__ G,
                                             float* __restrict__ nrm)
{
    int p = threadIdx.x;
    int py = p >> 4, px = p & 15;
    float s = 0.f;
    #pragma unroll
    for (int dy = -1; dy <= 1; dy++)
        #pragma unroll
        for (int dx = -1; dx <= 1; dx++) {
            int qy = py + dy, qx = px + dx;
            if (qy >= 0 && qy < 16 && qx >= 0 && qx < 16) {
                int q = qy * 16 + qx;
                s += G[q * 256 + q];
            }
        }
    nrm[p] = fmaxf(sqrtf(s), 1e-4f);
}

// 6) yi from gram (9 shifted adds) + column softmax over p (scale 10).
//    One block per s; thread = p.
__global__ __launch_bounds__(256) void k_yis(const float* __restrict__ G,
                                             const float* __restrict__ nrm,
                                             float* __restrict__ yis)
{
    __shared__ float red[256];
    int s = blockIdx.x, p = threadIdx.x;
    int sy = s >> 4, sx = s & 15;
    int py = p >> 4, px = p & 15;
    float raw = 0.f;
    #pragma unroll
    for (int dy = -1; dy <= 1; dy++)
        #pragma unroll
        for (int dx = -1; dx <= 1; dx++) {
            int qy = py + dy, qx = px + dx, ry = sy + dy, rx = sx + dx;
            if (qy >= 0 && qy < 16 && qx >= 0 && qx < 16 &&
                ry >= 0 && ry < 16 && rx >= 0 && rx < 16)
                raw += G[(qy * 16 + qx) * 256 + ry * 16 + rx];
        }
    float v = 10.f * raw / nrm[p];
    float mx = blockReduceMax(v, red);
    float e = expf(v - mx);
    float ssum = blockReduceSum(e, red);
    yis[p * 256 + s] = e / ssum;
}

// 7) deconv weights Wk[ky*4+kx][c][p] = b[c, 2py+2-ky, 2px+2-kx] (0 OOB)
__global__ __launch_bounds__(256) void k_buildWk(const float* __restrict__ outres,
                                                 float* __restrict__ Wk)
{
    int idx = blockIdx.x * 256 + threadIdx.x;   // 16*512*256
    int p = idx & 255, c = (idx >> 8) & 511, kidx = idx >> 17;
    int ky = kidx >> 2, kx = kidx & 3;
    int row = 2 * (p >> 4) + 2 - ky;
    int col = 2 * (p & 15) + 2 - kx;
    float v = 0.f;
    if (row >= 0 && row < 32 && col >= 0 && col < 32)
        v = outres[c * 1024 + row * 32 + col];
    Wk[idx] = v;
}

// 8) deconv gather: ralout[c,oy,ox] = 0.25 * sum over <=4 valid (ky,kx) taps
__global__ __launch_bounds__(256) void k_gather(const float* __restrict__ Tb,
                                                float* __restrict__ ralout)
{
    int idx = blockIdx.x * 256 + threadIdx.x;   // 524288
    int o = idx & 1023, c = idx >> 10;
    int oy = o >> 5, ox = o & 31;
    int kyv[2], syv[2], kxv[2], sxv[2];
    if (oy & 1) { kyv[0] = 1; syv[0] = (oy - 1) >> 1; kyv[1] = 3; syv[1] = (oy + 1) >> 1; }
    else        { kyv[0] = 0; syv[0] = (oy >> 1) - 1; kyv[1] = 2; syv[1] = oy >> 1; }
    if (ox & 1) { kxv[0] = 1; sxv[0] = (ox - 1) >> 1; kxv[1] = 3; sxv[1] = (ox + 1) >> 1; }
    else        { kxv[0] = 0; sxv[0] = (ox >> 1) - 1; kxv[1] = 2; sxv[1] = ox >> 1; }
    float acc = 0.f;
    #pragma unroll
    for (int a = 0; a < 2; a++) {
        if (syv[a] < 0 || syv[a] > 15) continue;
        #pragma unroll
        for (int b = 0; b < 2; b++) {
            if (sxv[b] < 0 || sxv[b] > 15) continue;
            int kidx = kyv[a] * 4 + kxv[b];
            acc += Tb[kidx * 131072 + c * 256 + syv[a] * 16 + sxv[b]];
        }
    }
    ralout[idx] = 0.25f * acc;
}

// 9) transpose [c][p] -> [p][c], plus sigmoid copy
__global__ void k_transpose(const float* __restrict__ in,
                            float* __restrict__ outT, float* __restrict__ sigT)
{
    __shared__ float tile[32][33];
    int ps = blockIdx.x * 32, cs = blockIdx.y * 32;
    int tx = threadIdx.x, ty = threadIdx.y;
    #pragma unroll
    for (int r = 0; r < 4; r++)
        tile[ty + r * 8][tx] = in[(cs + ty + r * 8) * 1024 + ps + tx];
    __syncthreads();
    #pragma unroll
    for (int r = 0; r < 4; r++) {
        int p = ps + ty + r * 8;
        float v = tile[tx][ty + r * 8];
        outT[p * 512 + cs + tx] = v;
        sigT[p * 512 + cs + tx] = 1.f / (1.f + expf(-v));
    }
}

// 10) csa: per-pixel 9-tap self-attention. One block per pixel p.
__global__ __launch_bounds__(256) void k_csa(const float* __restrict__ sigT,
                                             const float* __restrict__ ralT,
                                             float* __restrict__ csab)
{
    __shared__ float red[256];
    __shared__ float a9[9];
    int p = blockIdx.x, t = threadIdx.x;
    int py = p >> 5, px = p & 31;
    int nb[9]; bool ok[9];
    #pragma unroll
    for (int d = 0; d < 9; d++) {
        int dy = d / 3 - 1, dx = d % 3 - 1;
        int y = py + dy, x = px + dx;
        ok[d] = (y >= 0 && y < 32 && x >= 0 && x < 32);
        nb[d] = ok[d] ? (y * 32 + x) : 0;
    }
    float loc[9] = {};
    for (int c = t; c < 512; c += 256) {
        float sv = sigT[p * 512 + c];
        #pragma unroll
        for (int d = 0; d < 9; d++)
            if (ok[d]) loc[d] += sv * sigT[nb[d] * 512 + c];
    }
    #pragma unroll
    for (int d = 0; d < 9; d++) {
        float r = blockReduceSum(loc[d], red);
        if (t == 0) a9[d] = r * (1.f / 512.f);
    }
    __syncthreads();
    float mx = -1e30f;
    #pragma unroll
    for (int d = 0; d < 9; d++) mx = fmaxf(mx, a9[d]);
    float wgt[9]; float ssum = 0.f;
    #pragma unroll
    for (int d = 0; d < 9; d++) { wgt[d] = expf(a9[d] - mx); ssum += wgt[d]; }
    float inv = 1.f / ssum;
    for (int c = t; c < 512; c += 256) {
        float acc = 0.f;
        #pragma unroll
        for (int d = 0; d < 9; d++)
            if (ok[d]) acc += wgt[d] * ralT[nb[d] * 512 + c];
        csab[p * 512 + c] = acc * inv;
    }
}

// 11) instance norm + leaky relu 0.2. One block per channel.
__global__ __launch_bounds__(256) void k_inorm_lrelu(const float* __restrict__ in,
                                                     float* __restrict__ out)
{
    __shared__ float red[256];
    int c = blockIdx.x, t = threadIdx.x;
    float v[4];
    #pragma unroll
    for (int q = 0; q < 4; q++) v[q] = in[c * 1024 + t + q * 256];
    float s  = v[0] + v[1] + v[2] + v[3];
    float sq = v[0]*v[0] + v[1]*v[1] + v[2]*v[2] + v[3]*v[3];
    s  = blockReduceSum(s,  red);
    sq = blockReduceSum(sq, red);
    float mean = s * (1.f / 1024.f);
    float var  = sq * (1.f / 1024.f) - mean * mean;
    float rstd = rsqrtf(var + 1e-5f);
    #pragma unroll
    for (int q = 0; q < 4; q++) {
        float z = (v[q] - mean) * rstd;
        out[c * 1024 + t + q * 256] = (z >= 0.f) ? z : 0.2f * z;
    }
}

// ---------------------------------------------------------------------------
extern "C" void kernel_launch(void* const* d_in, const int* in_sizes, int n_in,
                              void* d_out, int out_size)
{
    const float* x      = (const float*)d_in[0];
    const float* gus    = (const float*)d_in[1];
    const float* w3     = (const float*)d_in[2];
    const float* w5     = (const float*)d_in[4];
    const float* w7     = (const float*)d_in[6];
    const float* fc_w   = (const float*)d_in[8];
    const float* fc_b   = (const float*)d_in[9];
    const float* fcs_w  = (const float*)d_in[10];
    const float* fcs_b  = (const float*)d_in[11];
    const float* down_w = (const float*)d_in[12];
    const float* fuse_w = (const float*)d_in[13];
    float* out = (float*)d_out;

    void* sp = nullptr;
    cudaGetSymbolAddress(&sp, g_scratch);
    float* S = (float*)sp;
    float* feas   = S + O_FEAS;
    float* bmean  = S + O_BMEAN;
    float* att    = S + O_ATT;
    float* outres = S + O_OUTRES;
    float* fdT    = S + O_FDT;
    float* G      = S + O_G;
    float* nrm    = S + O_NRM;
    float* yis    = S + O_YIS;
    float* Wk     = S + O_WK;
    float* Tb     = S + O_TB;
    float* ralout = S + O_RALOUT;
    float* ralT   = S + O_RALT;
    float* sigT   = S + O_SIGT;
    float* gusb   = S + O_GUSB;
    float* csab   = S + O_CSAB;
    float* y1raw  = S + O_Y1RAW;
    float* y1     = S + O_Y1;
    float* y2raw  = S + O_Y2RAW;

    // skconv branches (bias is mathematically dead under instance norm)
    k_skconv<3><<<512, 256, (34 * 34 + 16 * 9)  * 4>>>(x, w3, feas,           bmean);
    k_skconv<5><<<512, 256, (36 * 36 + 16 * 25) * 4>>>(x, w5, feas + 524288,  bmean + 512);
    k_skconv<7><<<512, 256, (38 * 38 + 16 * 49) * 4>>>(x, w7, feas + 1048576, bmean + 1024);
    k_att<<<1, 512>>>(bmean, fc_w, fc_b, fcs_w, fcs_b, att);
    k_mix<<<2048, 256>>>(feas, att, outres);

    // ral via gram matrix + 16 batched GEMMs
    k_fd<<<512, 256>>>(outres, fdT);
    gemm_abt<<<dim3(4, 4, 1), 256>>>(fdT, fdT, G, 256, 256, 512);
    k_nrm<<<1, 256>>>(G, nrm);
    k_yis<<<256, 256>>>(G, nrm, yis);
    k_buildWk<<<8192, 256>>>(outres, Wk);
    gemm_ab<<<dim3(4, 8, 16), 256>>>(Wk, yis, yis, 256, Tb, 512, 256, 256,
                                     131072L, 0L, 131072L);
    k_gather<<<2048, 256>>>(Tb, ralout);
    k_transpose<<<dim3(32, 16), dim3(32, 8)>>>(ralout, ralT, sigT);

    // gus einsum: [p][c] = gus[p,:] . ralout[c,:]
    gemm_abt<<<dim3(8, 16, 1), 256>>>(gus, ralout, gusb, 1024, 512, 1024);
    // csa branch
    k_csa<<<1024, 256>>>(sigT, ralT, csab);
    // down 1x1 conv (concat handled via split-B) + inorm + lrelu
    gemm_ab<<<dim3(16, 8, 1), 256>>>(down_w, gusb, csab, 512, y1raw,
                                     512, 1024, 1024, 0L, 0L, 0L);
    k_inorm_lrelu<<<512, 256>>>(y1raw, y1);
    // fuse 1x1 conv + inorm + lrelu -> output
    gemm_ab<<<dim3(16, 8, 1), 256>>>(fuse_w, y1, outres, 512, y2raw,
                                     512, 1024, 1024, 0L, 0L, 0L);
    k_inorm_lrelu<<<512, 256>>>(y2raw, out);
}

// round 2
// speedup vs baseline: 1.2473x; 1.2473x over previous
#include <cuda_runtime.h>
#include <math.h>

// ---------------------------------------------------------------------------
// Problem constants: x (1,512,32,32); all spatial = 32x32 = 1024 px.
// ---------------------------------------------------------------------------
static constexpr long O_FEAS   = 0;            // 3 * 524288
static constexpr long O_BMEAN  = 1572864;      // 1536
static constexpr long O_ATT    = 1574400;      // 1536
static constexpr long O_OUTRES = 1575936;      // 524288
static constexpr long O_FDT    = 2100224;      // 131072  fd^T [s][c]
static constexpr long O_G      = 2231296;      // 65536   gram 256x256
static constexpr long O_FZ     = 2296832;      // 32 (was nrm)
static constexpr long O_YIS    = 2297088;      // 65536   softmaxed yi [p][s]
static constexpr long O_WK     = 2362624;      // 2097152 Wk[16][512][256]
static constexpr long O_TB     = 4459776;      // 2097152 T[16][512][256]
static constexpr long O_RALOUT = 6556928;      // 524288  [c][hw]
static constexpr long O_RALT   = 7081216;      // 524288  [hw][c]
static constexpr long O_SIGT   = 7605504;      // 524288  sigmoid [hw][c]
static constexpr long O_GUSB   = 8129792;      // 524288  [p][c] flat
static constexpr long O_CSAB   = 8654080;      // 524288  [p][c] flat
static constexpr long O_Y1RAW  = 9178368;
static constexpr long O_Y1     = 9702656;
static constexpr long O_Y2RAW  = 10226944;
static constexpr long SCRATCH  = 10751232;

__device__ __align__(256) float g_scratch[SCRATCH];

// ---------------------------------------------------------------------------
// Cheap block reductions for blockDim.x == 256 (2 syncs, shfl-based).
// red must have >= 9 floats of shared.
// ---------------------------------------------------------------------------
__device__ __forceinline__ float blockSum256(float v, float* red) {
    int lane = threadIdx.x & 31, w = threadIdx.x >> 5;
    #pragma unroll
    for (int o = 16; o; o >>= 1) v += __shfl_down_sync(0xffffffffu, v, o);
    if (lane == 0) red[w] = v;
    __syncthreads();
    if (threadIdx.x == 0) {
        float s = 0.f;
        #pragma unroll
        for (int i = 0; i < 8; i++) s += red[i];
        red[8] = s;
    }
    __syncthreads();
    return red[8];
}
__device__ __forceinline__ float blockMax256(float v, float* red) {
    int lane = threadIdx.x & 31, w = threadIdx.x >> 5;
    #pragma unroll
    for (int o = 16; o; o >>= 1) v = fmaxf(v, __shfl_down_sync(0xffffffffu, v, o));
    if (lane == 0) red[w] = v;
    __syncthreads();
    if (threadIdx.x == 0) {
        float s = red[0];
        #pragma unroll
        for (int i = 1; i < 8; i++) s = fmaxf(s, red[i]);
        red[8] = s;
    }
    __syncthreads();
    return red[8];
}

// ---------------------------------------------------------------------------
// 1) Grouped conv + instance norm + ReLU + channel mean. Bias is dead.
// ---------------------------------------------------------------------------
template <int KW>
__global__ __launch_bounds__(256) void k_skconv(
    const float* __restrict__ x, const float* __restrict__ w,
    float* __restrict__ fea, float* __restrict__ bmean)
{
    constexpr int PAD  = (KW - 1) / 2;
    constexpr int S    = 32 + 2 * PAD;
    constexpr int TAPS = KW * KW;
    extern __shared__ float sm[];
    float* wsm = sm;
    float* xt  = sm + 16 * TAPS;
    __shared__ float red[9];

    const int c = blockIdx.x;
    const int t = threadIdx.x;
    const int g = c >> 4;
    const int px0 = t & 31, py0 = t >> 5;

    for (int i = t; i < 16 * TAPS; i += 256) wsm[i] = w[c * 16 * TAPS + i];

    float acc[4] = {0.f, 0.f, 0.f, 0.f};
    for (int ci = 0; ci < 16; ci++) {
        __syncthreads();
        const float* xc = x + (g * 16 + ci) * 1024;
        for (int i = t; i < S * S; i += 256) {
            int r  = i / S - PAD;
            int cc = i % S - PAD;
            xt[i] = (r >= 0 && r < 32 && cc >= 0 && cc < 32) ? xc[r * 32 + cc] : 0.f;
        }
        __syncthreads();
        const float* wc = wsm + ci * TAPS;
        #pragma unroll
        for (int q = 0; q < 4; q++) {
            const float* xb = xt + (py0 + q * 8) * S + px0;
            float a = acc[q];
            #pragma unroll
            for (int ky = 0; ky < KW; ky++) {
                const float* xr = xb + ky * S;
                const float* wr = wc + ky * KW;
                #pragma unroll
                for (int kx = 0; kx < KW; kx++) a += wr[kx] * xr[kx];
            }
            acc[q] = a;
        }
    }
    __syncthreads();
    float s  = acc[0] + acc[1] + acc[2] + acc[3];
    float sq = acc[0]*acc[0] + acc[1]*acc[1] + acc[2]*acc[2] + acc[3]*acc[3];
    s  = blockSum256(s,  red);
    sq = blockSum256(sq, red);
    float mean = s * (1.f / 1024.f);
    float var  = sq * (1.f / 1024.f) - mean * mean;
    float rstd = rsqrtf(var + 1e-5f);
    float rsum = 0.f;
    #pragma unroll
    for (int q = 0; q < 4; q++) {
        float v = (acc[q] - mean) * rstd;
        v = fmaxf(v, 0.f);
        fea[c * 1024 + (py0 + q * 8) * 32 + px0] = v;
        rsum += v;
    }
    rsum = blockSum256(rsum, red);
    if (t == 0) bmean[c] = rsum * (1.f / 1024.f);
}

// ---------------------------------------------------------------------------
// 2a) fea_z: 32 blocks, one per output dim d.
// ---------------------------------------------------------------------------
__global__ __launch_bounds__(256) void k_fcz(
    const float* __restrict__ bmean, const float* __restrict__ fc_w,
    const float* __restrict__ fc_b, float* __restrict__ fz)
{
    __shared__ float red[9];
    int d = blockIdx.x, t = threadIdx.x;
    float a = 0.f;
    for (int c = t; c < 512; c += 256) {
        float s = bmean[c] + bmean[512 + c] + bmean[1024 + c];
        a += s * fc_w[d * 512 + c];
    }
    a = blockSum256(a, red);
    if (t == 0) fz[d] = a + fc_b[d];
}

// 2b) per-channel 3-way softmax. grid 4 x 128.
__global__ __launch_bounds__(128) void k_att2(
    const float* __restrict__ fz, const float* __restrict__ fcs_w,
    const float* __restrict__ fcs_b, float* __restrict__ att)
{
    __shared__ float sz[32];
    int t = threadIdx.x;
    int c = blockIdx.x * 128 + t;
    if (t < 32) sz[t] = fz[t];
    __syncthreads();
    float av[3];
    #pragma unroll
    for (int m = 0; m < 3; m++) {
        float a = fcs_b[m * 512 + c];
        const float* fw = fcs_w + (m * 512 + c) * 32;
        #pragma unroll
        for (int d = 0; d < 32; d++) a += sz[d] * fw[d];
        av[m] = a;
    }
    float mx = fmaxf(av[0], fmaxf(av[1], av[2]));
    float e0 = expf(av[0] - mx), e1 = expf(av[1] - mx), e2 = expf(av[2] - mx);
    float inv = 1.f / (e0 + e1 + e2);
    att[c] = e0 * inv; att[512 + c] = e1 * inv; att[1024 + c] = e2 * inv;
}

// 3) mix + downsample-transpose fused
__global__ __launch_bounds__(256) void k_mix_fd(const float* __restrict__ feas,
                                                const float* __restrict__ att,
                                                float* __restrict__ outres,
                                                float* __restrict__ fdT)
{
    int idx = blockIdx.x * 256 + threadIdx.x;
    int c = idx >> 10, o = idx & 1023;
    float v = att[c] * feas[idx] + att[512 + c] * feas[524288 + idx]
            + att[1024 + c] * feas[1048576 + idx];
    outres[idx] = v;
    int oy = o >> 5, ox = o & 31;
    if (!(oy & 1) && !(ox & 1)) {
        int s = (oy >> 1) * 16 + (ox >> 1);
        fdT[s * 512 + c] = v;
    }
}

// ---------------------------------------------------------------------------
// Tiled SGEMM, 64x64 tile, BK=16, 256 thr, 4x4 microtile, global prefetch.
// ---------------------------------------------------------------------------
__global__ __launch_bounds__(256) void gemm_ab(
    const float* __restrict__ A, const float* __restrict__ B1,
    const float* __restrict__ B2, int K1, float* __restrict__ C,
    int M, int N, int K, long sA, long sB, long sC)
{
    A  += (long)blockIdx.z * sA;
    B1 += (long)blockIdx.z * sB;
    B2 += (long)blockIdx.z * sB;
    C  += (long)blockIdx.z * sC;
    __shared__ float As[16][68];
    __shared__ float Bs[16][68];
    int tid = threadIdx.x;
    int tx = tid & 15, ty = tid >> 4;
    int m0 = blockIdx.y * 64, n0 = blockIdx.x * 64;
    int a_m = tid >> 2, a_k4 = (tid & 3) * 4;
    int b_k = tid >> 4, b_n4 = (tid & 15) * 4;
    float acc[4][4] = {};
    const float* aptr = A + (long)(m0 + a_m) * K + a_k4;
    float4 av = *(const float4*)(aptr);
    const float* src0 = (b_k < K1) ? (B1 + (long)b_k * N) : (B2 + (long)(b_k - K1) * N);
    float4 bv = *(const float4*)(src0 + n0 + b_n4);
    for (int kt = 0; kt < K; kt += 16) {
        As[a_k4 + 0][a_m] = av.x; As[a_k4 + 1][a_m] = av.y;
        As[a_k4 + 2][a_m] = av.z; As[a_k4 + 3][a_m] = av.w;
        *(float4*)&Bs[b_k][b_n4] = bv;
        __syncthreads();
        if (kt + 16 < K) {
            av = *(const float4*)(aptr + kt + 16);
            int gk = kt + 16 + b_k;
            const float* src = (gk < K1) ? (B1 + (long)gk * N) : (B2 + (long)(gk - K1) * N);
            bv = *(const float4*)(src + n0 + b_n4);
        }
        #pragma unroll
        for (int kk = 0; kk < 16; kk++) {
            float4 a = *(const float4*)&As[kk][ty * 4];
            float4 b = *(const float4*)&Bs[kk][tx * 4];
            acc[0][0] += a.x * b.x; acc[0][1] += a.x * b.y; acc[0][2] += a.x * b.z; acc[0][3] += a.x * b.w;
            acc[1][0] += a.y * b.x; acc[1][1] += a.y * b.y; acc[1][2] += a.y * b.z; acc[1][3] += a.y * b.w;
            acc[2][0] += a.z * b.x; acc[2][1] += a.z * b.y; acc[2][2] += a.z * b.z; acc[2][3] += a.z * b.w;
            acc[3][0] += a.w * b.x; acc[3][1] += a.w * b.y; acc[3][2] += a.w * b.z; acc[3][3] += a.w * b.w;
        }
        __syncthreads();
    }
    #pragma unroll
    for (int i = 0; i < 4; i++) {
        float4 v = make_float4(acc[i][0], acc[i][1], acc[i][2], acc[i][3]);
        *(float4*)(C + (long)(m0 + ty * 4 + i) * N + n0 + tx * 4) = v;
    }
}

__global__ __launch_bounds__(256) void gemm_abt(
    const float* __restrict__ A, const float* __restrict__ B,
    float* __restrict__ C, int M, int N, int K)
{
    __shared__ float As[16][68];
    __shared__ float Bs[16][68];
    int tid = threadIdx.x;
    int tx = tid & 15, ty = tid >> 4;
    int m0 = blockIdx.y * 64, n0 = blockIdx.x * 64;
    int a_m = tid >> 2, a_k4 = (tid & 3) * 4;
    float acc[4][4] = {};
    const float* aptr = A + (long)(m0 + a_m) * K + a_k4;
    const float* bptr = B + (long)(n0 + a_m) * K + a_k4;
    float4 av = *(const float4*)(aptr);
    float4 bv = *(const float4*)(bptr);
    for (int kt = 0; kt < K; kt += 16) {
        As[a_k4 + 0][a_m] = av.x; As[a_k4 + 1][a_m] = av.y;
        As[a_k4 + 2][a_m] = av.z; As[a_k4 + 3][a_m] = av.w;
        Bs[a_k4 + 0][a_m] = bv.x; Bs[a_k4 + 1][a_m] = bv.y;
        Bs[a_k4 + 2][a_m] = bv.z; Bs[a_k4 + 3][a_m] = bv.w;
        __syncthreads();
        if (kt + 16 < K) {
            av = *(const float4*)(aptr + kt + 16);
            bv = *(const float4*)(bptr + kt + 16);
        }
        #pragma unroll
        for (int kk = 0; kk < 16; kk++) {
            float4 a = *(const float4*)&As[kk][ty * 4];
            float4 b = *(const float4*)&Bs[kk][tx * 4];
            acc[0][0] += a.x * b.x; acc[0][1] += a.x * b.y; acc[0][2] += a.x * b.z; acc[0][3] += a.x * b.w;
            acc[1][0] += a.y * b.x; acc[1][1] += a.y * b.y; acc[1][2] += a.y * b.z; acc[1][3] += a.y * b.w;
            acc[2][0] += a.z * b.x; acc[2][1] += a.z * b.y; acc[2][2] += a.z * b.z; acc[2][3] += a.z * b.w;
            acc[3][0] += a.w * b.x; acc[3][1] += a.w * b.y; acc[3][2] += a.w * b.z; acc[3][3] += a.w * b.w;
        }
        __syncthreads();
    }
    #pragma unroll
    for (int i = 0; i < 4; i++) {
        float4 v = make_float4(acc[i][0], acc[i][1], acc[i][2], acc[i][3]);
        *(float4*)(C + (long)(m0 + ty * 4 + i) * N + n0 + tx * 4) = v;
    }
}

// 6) yi from gram (9 shifted adds, per-thread nrm from diag) + col softmax.
__global__ __launch_bounds__(256) void k_yis(const float* __restrict__ G,
                                             float* __restrict__ yis)
{
    __shared__ float red[9];
    int s = blockIdx.x, p = threadIdx.x;
    int sy = s >> 4, sx = s & 15;
    int py = p >> 4, px = p & 15;
    float raw = 0.f, nsum = 0.f;
    #pragma unroll
    for (int dy = -1; dy <= 1; dy++)
        #pragma unroll
        for (int dx = -1; dx <= 1; dx++) {
            int qy = py + dy, qx = px + dx;
            if (qy >= 0 && qy < 16 && qx >= 0 && qx < 16) {
                int q = qy * 16 + qx;
                nsum += G[q * 256 + q];
                int ry = sy + dy, rx = sx + dx;
                if (ry >= 0 && ry < 16 && rx >= 0 && rx < 16)
                    raw += G[q * 256 + ry * 16 + rx];
            }
        }
    float nrm = fmaxf(sqrtf(nsum), 1e-4f);
    float v = 10.f * raw / nrm;
    float mx = blockMax256(v, red);
    float e = expf(v - mx);
    float ssum = blockSum256(e, red);
    yis[p * 256 + s] = e / ssum;
}

// 7) deconv weights
__global__ __launch_bounds__(256) void k_buildWk(const float* __restrict__ outres,
                                                 float* __restrict__ Wk)
{
    int idx = blockIdx.x * 256 + threadIdx.x;
    int p = idx & 255, c = (idx >> 8) & 511, kidx = idx >> 17;
    int ky = kidx >> 2, kx = kidx & 3;
    int row = 2 * (p >> 4) + 2 - ky;
    int col = 2 * (p & 15) + 2 - kx;
    float v = 0.f;
    if (row >= 0 && row < 32 && col >= 0 && col < 32)
        v = outres[c * 1024 + row * 32 + col];
    Wk[idx] = v;
}

// 8+9) fused deconv-gather + transpose + sigmoid
__global__ void k_gather_tr(const float* __restrict__ Tb,
                            float* __restrict__ ralout,
                            float* __restrict__ ralT, float* __restrict__ sigT)
{
    __shared__ float tile[32][33];
    int ps = blockIdx.x * 32, cs = blockIdx.y * 32;
    int tx = threadIdx.x, ty = threadIdx.y;
    int p = ps + tx;
    int oy = p >> 5, ox = p & 31;
    int kyv[2], syv[2], kxv[2], sxv[2];
    if (oy & 1) { kyv[0] = 1; syv[0] = (oy - 1) >> 1; kyv[1] = 3; syv[1] = (oy + 1) >> 1; }
    else        { kyv[0] = 0; syv[0] = (oy >> 1) - 1; kyv[1] = 2; syv[1] = oy >> 1; }
    if (ox & 1) { kxv[0] = 1; sxv[0] = (ox - 1) >> 1; kxv[1] = 3; sxv[1] = (ox + 1) >> 1; }
    else        { kxv[0] = 0; sxv[0] = (ox >> 1) - 1; kxv[1] = 2; sxv[1] = ox >> 1; }
    #pragma unroll
    for (int r = 0; r < 4; r++) {
        int c = cs + ty + 8 * r;
        float acc = 0.f;
        #pragma unroll
        for (int a = 0; a < 2; a++) {
            if (syv[a] < 0 || syv[a] > 15) continue;
            #pragma unroll
            for (int b = 0; b < 2; b++) {
                if (sxv[b] < 0 || sxv[b] > 15) continue;
                int kidx = kyv[a] * 4 + kxv[b];
                acc += Tb[kidx * 131072 + c * 256 + syv[a] * 16 + sxv[b]];
            }
        }
        float v = 0.25f * acc;
        ralout[c * 1024 + p] = v;
        tile[ty + 8 * r][tx] = v;
    }
    __syncthreads();
    #pragma unroll
    for (int r = 0; r < 4; r++) {
        int pp = ps + ty + 8 * r, cc = cs + tx;
        float v = tile[tx][ty + 8 * r];
        ralT[pp * 512 + cc] = v;
        sigT[pp * 512 + cc] = 1.f / (1.f + expf(-v));
    }
}

// 10) csa with shfl reductions
__global__ __launch_bounds__(256) void k_csa(const float* __restrict__ sigT,
                                             const float* __restrict__ ralT,
                                             float* __restrict__ csab)
{
    __shared__ float ws[8][9];
    __shared__ float a9[9];
    int p = blockIdx.x, t = threadIdx.x;
    int lane = t & 31, w = t >> 5;
    int py = p >> 5, px = p & 31;
    int nb[9]; bool ok[9];
    #pragma unroll
    for (int d = 0; d < 9; d++) {
        int dy = d / 3 - 1, dx = d % 3 - 1;
        int y = py + dy, x = px + dx;
        ok[d] = (y >= 0 && y < 32 && x >= 0 && x < 32);
        nb[d] = ok[d] ? (y * 32 + x) : 0;
    }
    float loc[9] = {};
    for (int c = t; c < 512; c += 256) {
        float sv = sigT[p * 512 + c];
        #pragma unroll
        for (int d = 0; d < 9; d++)
            if (ok[d]) loc[d] += sv * sigT[nb[d] * 512 + c];
    }
    #pragma unroll
    for (int d = 0; d < 9; d++) {
        #pragma unroll
        for (int o = 16; o; o >>= 1) loc[d] += __shfl_down_sync(0xffffffffu, loc[d], o);
        if (lane == 0) ws[w][d] = loc[d];
    }
    __syncthreads();
    if (t < 9) {
        float s = 0.f;
        #pragma unroll
        for (int i = 0; i < 8; i++) s += ws[i][t];
        a9[t] = s * (1.f / 512.f);
    }
    __syncthreads();
    float mx = -1e30f;
    #pragma unroll
    for (int d = 0; d < 9; d++) mx = fmaxf(mx, a9[d]);
    float wgt[9]; float ssum = 0.f;
    #pragma unroll
    for (int d = 0; d < 9; d++) { wgt[d] = expf(a9[d] - mx); ssum += wgt[d]; }
    float inv = 1.f / ssum;
    for (int c = t; c < 512; c += 256) {
        float acc = 0.f;
        #pragma unroll
        for (int d = 0; d < 9; d++)
            if (ok[d]) acc += wgt[d] * ralT[nb[d] * 512 + c];
        csab[p * 512 + c] = acc * inv;
    }
}

// 11) instance norm + leaky relu 0.2
__global__ __launch_bounds__(256) void k_inorm_lrelu(const float* __restrict__ in,
                                                     float* __restrict__ out)
{
    __shared__ float red[9];
    int c = blockIdx.x, t = threadIdx.x;
    float v[4];
    #pragma unroll
    for (int q = 0; q < 4; q++) v[q] = in[c * 1024 + t + q * 256];
    float s  = v[0] + v[1] + v[2] + v[3];
    float sq = v[0]*v[0] + v[1]*v[1] + v[2]*v[2] + v[3]*v[3];
    s  = blockSum256(s,  red);
    sq = blockSum256(sq, red);
    float mean = s * (1.f / 1024.f);
    float var  = sq * (1.f / 1024.f) - mean * mean;
    float rstd = rsqrtf(var + 1e-5f);
    #pragma unroll
    for (int q = 0; q < 4; q++) {
        float z = (v[q] - mean) * rstd;
        out[c * 1024 + t + q * 256] = (z >= 0.f) ? z : 0.2f * z;
    }
}

// ---------------------------------------------------------------------------
extern "C" void kernel_launch(void* const* d_in, const int* in_sizes, int n_in,
                              void* d_out, int out_size)
{
    const float* x      = (const float*)d_in[0];
    const float* gus    = (const float*)d_in[1];
    const float* w3     = (const float*)d_in[2];
    const float* w5     = (const float*)d_in[4];
    const float* w7     = (const float*)d_in[6];
    const float* fc_w   = (const float*)d_in[8];
    const float* fc_b   = (const float*)d_in[9];
    const float* fcs_w  = (const float*)d_in[10];
    const float* fcs_b  = (const float*)d_in[11];
    const float* down_w = (const float*)d_in[12];
    const float* fuse_w = (const float*)d_in[13];
    float* out = (float*)d_out;

    void* sp = nullptr;
    cudaGetSymbolAddress(&sp, g_scratch);
    float* S = (float*)sp;
    float* feas   = S + O_FEAS;
    float* bmean  = S + O_BMEAN;
    float* att    = S + O_ATT;
    float* outres = S + O_OUTRES;
    float* fdT    = S + O_FDT;
    float* G      = S + O_G;
    float* fz     = S + O_FZ;
    float* yis    = S + O_YIS;
    float* Wk     = S + O_WK;
    float* Tb     = S + O_TB;
    float* ralout = S + O_RALOUT;
    float* ralT   = S + O_RALT;
    float* sigT   = S + O_SIGT;
    float* gusb   = S + O_GUSB;
    float* csab   = S + O_CSAB;
    float* y1raw  = S + O_Y1RAW;
    float* y1     = S + O_Y1;
    float* y2raw  = S + O_Y2RAW;

    static cudaStream_t s1 = nullptr, s2 = nullptr;
    static cudaEvent_t evA, ev1, ev2, evB, ev3, evC, ev4;
    if (!s1) {
        cudaStreamCreateWithFlags(&s1, cudaStreamNonBlocking);
        cudaStreamCreateWithFlags(&s2, cudaStreamNonBlocking);
        cudaEventCreateWithFlags(&evA, cudaEventDisableTiming);
        cudaEventCreateWithFlags(&ev1, cudaEventDisableTiming);
        cudaEventCreateWithFlags(&ev2, cudaEventDisableTiming);
        cudaEventCreateWithFlags(&evB, cudaEventDisableTiming);
        cudaEventCreateWithFlags(&ev3, cudaEventDisableTiming);
        cudaEventCreateWithFlags(&evC, cudaEventDisableTiming);
        cudaEventCreateWithFlags(&ev4, cudaEventDisableTiming);
    }

    // --- fork: 3 skconv branches concurrent ---
    cudaEventRecord(evA, 0);
    cudaStreamWaitEvent(s1, evA, 0);
    cudaStreamWaitEvent(s2, evA, 0);
    k_skconv<3><<<512, 256, (34 * 34 + 16 * 9)  * 4, 0 >>>(x, w3, feas,           bmean);
    k_skconv<5><<<512, 256, (36 * 36 + 16 * 25) * 4, s1>>>(x, w5, feas + 524288,  bmean + 512);
    k_skconv<7><<<512, 256, (38 * 38 + 16 * 49) * 4, s2>>>(x, w7, feas + 1048576, bmean + 1024);
    cudaEventRecord(ev1, s1);
    cudaEventRecord(ev2, s2);
    cudaStreamWaitEvent(0, ev1, 0);
    cudaStreamWaitEvent(0, ev2, 0);

    k_fcz <<<32, 256>>>(bmean, fc_w, fc_b, fz);
    k_att2<<<4, 128>>>(fz, fcs_w, fcs_b, att);
    k_mix_fd<<<2048, 256>>>(feas, att, outres, fdT);

    // --- fork: buildWk on s1, gram+yis on 0 ---
    cudaEventRecord(evB, 0);
    cudaStreamWaitEvent(s1, evB, 0);
    k_buildWk<<<8192, 256, 0, s1>>>(outres, Wk);
    gemm_abt<<<dim3(4, 4, 1), 256>>>(fdT, fdT, G, 256, 256, 512);
    k_yis<<<256, 256>>>(G, yis);
    cudaEventRecord(ev3, s1);
    cudaStreamWaitEvent(0, ev3, 0);

    gemm_ab<<<dim3(4, 8, 16), 256>>>(Wk, yis, yis, 256, Tb, 512, 256, 256,
                                     131072L, 0L, 131072L);
    k_gather_tr<<<dim3(32, 16), dim3(32, 8)>>>(Tb, ralout, ralT, sigT);

    // --- fork: csa on s1, gus gemm on 0 ---
    cudaEventRecord(evC, 0);
    cudaStreamWaitEvent(s1, evC, 0);
    k_csa<<<1024, 256, 0, s1>>>(sigT, ralT, csab);
    gemm_abt<<<dim3(8, 16, 1), 256>>>(gus, ralout, gusb, 1024, 512, 1024);
    cudaEventRecord(ev4, s1);
    cudaStreamWaitEvent(0, ev4, 0);

    gemm_ab<<<dim3(16, 8, 1), 256>>>(down_w, gusb, csab, 512, y1raw,
                                     512, 1024, 1024, 0L, 0L, 0L);
    k_inorm_lrelu<<<512, 256>>>(y1raw, y1);
    gemm_ab<<<dim3(16, 8, 1), 256>>>(fuse_w, y1, outres, 512, y2raw,
                                     512, 1024, 1024, 0L, 0L, 0L);
    k_inorm_lrelu<<<512, 256>>>(y2raw, out);
}

// round 3
// speedup vs baseline: 1.4302x; 1.1466x over previous
#include <cuda_runtime.h>
#include <math.h>

// ---------------------------------------------------------------------------
// Problem constants: x (1,512,32,32); all spatial = 32x32 = 1024 px.
// ---------------------------------------------------------------------------
static constexpr long O_FEAS   = 0;            // 3 * 524288
static constexpr long O_BMEAN  = 1572864;      // 1536
static constexpr long O_ATT    = 1574400;      // 1536
static constexpr long O_OUTRES = 1575936;      // 524288
static constexpr long O_FDT    = 2100224;      // 131072  fd^T [s][c]
static constexpr long O_G      = 2231296;      // 65536   gram 256x256
static constexpr long O_FZ     = 2296832;      // 32
static constexpr long O_YIS    = 2297088;      // 65536   softmaxed yi [p][s]
static constexpr long O_MM     = 2362624;      // 1048576 M[q][o] 1024x1024
static constexpr long O_RALOUT = 6556928;      // 524288  [c][hw]
static constexpr long O_RALT   = 7081216;      // 524288  [hw][c]
static constexpr long O_SIGT   = 7605504;      // 524288  sigmoid [hw][c]
static constexpr long O_GUSB   = 8129792;      // 524288  [p][c] flat
static constexpr long O_CSAB   = 8654080;      // 524288  [p][c] flat
static constexpr long O_Y1RAW  = 9178368;
static constexpr long O_Y1     = 9702656;
static constexpr long O_Y2RAW  = 10226944;
static constexpr long SCRATCH  = 10751232;

__device__ __align__(256) float g_scratch[SCRATCH];

// ---------------------------------------------------------------------------
__device__ __forceinline__ float blockSum256(float v, float* red) {
    int lane = threadIdx.x & 31, w = threadIdx.x >> 5;
    #pragma unroll
    for (int o = 16; o; o >>= 1) v += __shfl_down_sync(0xffffffffu, v, o);
    if (lane == 0) red[w] = v;
    __syncthreads();
    if (threadIdx.x == 0) {
        float s = 0.f;
        #pragma unroll
        for (int i = 0; i < 8; i++) s += red[i];
        red[8] = s;
    }
    __syncthreads();
    return red[8];
}
__device__ __forceinline__ float blockMax256(float v, float* red) {
    int lane = threadIdx.x & 31, w = threadIdx.x >> 5;
    #pragma unroll
    for (int o = 16; o; o >>= 1) v = fmaxf(v, __shfl_down_sync(0xffffffffu, v, o));
    if (lane == 0) red[w] = v;
    __syncthreads();
    if (threadIdx.x == 0) {
        float s = red[0];
        #pragma unroll
        for (int i = 1; i < 8; i++) s = fmaxf(s, red[i]);
        red[8] = s;
    }
    __syncthreads();
    return red[8];
}

__device__ __forceinline__ unsigned cvt_tf32(float x) {
    unsigned r;
    asm("cvt.rna.tf32.f32 %0, %1;" : "=r"(r) : "f"(x));
    return r;
}
__device__ __forceinline__ void mma_tf32(float c[4], const unsigned a[4],
                                         const unsigned b[2]) {
    asm volatile(
        "mma.sync.aligned.m16n8k8.row.col.f32.tf32.tf32.f32 "
        "{%0,%1,%2,%3},{%4,%5,%6,%7},{%8,%9},{%0,%1,%2,%3};"
        : "+f"(c[0]), "+f"(c[1]), "+f"(c[2]), "+f"(c[3])
        : "r"(a[0]), "r"(a[1]), "r"(a[2]), "r"(a[3]), "r"(b[0]), "r"(b[1]));
}

// ---------------------------------------------------------------------------
// 1) Grouped conv + instance norm + ReLU + channel mean. Bias is dead.
// ---------------------------------------------------------------------------
template <int KW>
__global__ __launch_bounds__(256) void k_skconv(
    const float* __restrict__ x, const float* __restrict__ w,
    float* __restrict__ fea, float* __restrict__ bmean)
{
    constexpr int PAD  = (KW - 1) / 2;
    constexpr int S    = 32 + 2 * PAD;
    constexpr int TAPS = KW * KW;
    extern __shared__ float sm[];
    float* wsm = sm;
    float* xt  = sm + 16 * TAPS;
    __shared__ float red[9];

    const int c = blockIdx.x;
    const int t = threadIdx.x;
    const int g = c >> 4;
    const int px0 = t & 31, py0 = t >> 5;

    for (int i = t; i < 16 * TAPS; i += 256) wsm[i] = w[c * 16 * TAPS + i];

    float acc[4] = {0.f, 0.f, 0.f, 0.f};
    for (int ci = 0; ci < 16; ci++) {
        __syncthreads();
        const float* xc = x + (g * 16 + ci) * 1024;
        for (int i = t; i < S * S; i += 256) {
            int r  = i / S - PAD;
            int cc = i % S - PAD;
            xt[i] = (r >= 0 && r < 32 && cc >= 0 && cc < 32) ? xc[r * 32 + cc] : 0.f;
        }
        __syncthreads();
        const float* wc = wsm + ci * TAPS;
        #pragma unroll
        for (int q = 0; q < 4; q++) {
            const float* xb = xt + (py0 + q * 8) * S + px0;
            float a = acc[q];
            #pragma unroll
            for (int ky = 0; ky < KW; ky++) {
                const float* xr = xb + ky * S;
                const float* wr = wc + ky * KW;
                #pragma unroll
                for (int kx = 0; kx < KW; kx++) a += wr[kx] * xr[kx];
            }
            acc[q] = a;
        }
    }
    __syncthreads();
    float s  = acc[0] + acc[1] + acc[2] + acc[3];
    float sq = acc[0]*acc[0] + acc[1]*acc[1] + acc[2]*acc[2] + acc[3]*acc[3];
    s  = blockSum256(s,  red);
    sq = blockSum256(sq, red);
    float mean = s * (1.f / 1024.f);
    float var  = sq * (1.f / 1024.f) - mean * mean;
    float rstd = rsqrtf(var + 1e-5f);
    float rsum = 0.f;
    #pragma unroll
    for (int q = 0; q < 4; q++) {
        float v = (acc[q] - mean) * rstd;
        v = fmaxf(v, 0.f);
        fea[c * 1024 + (py0 + q * 8) * 32 + px0] = v;
        rsum += v;
    }
    rsum = blockSum256(rsum, red);
    if (t == 0) bmean[c] = rsum * (1.f / 1024.f);
}

// 2a) fea_z
__global__ __launch_bounds__(256) void k_fcz(
    const float* __restrict__ bmean, const float* __restrict__ fc_w,
    const float* __restrict__ fc_b, float* __restrict__ fz)
{
    __shared__ float red[9];
    int d = blockIdx.x, t = threadIdx.x;
    float a = 0.f;
    for (int c = t; c < 512; c += 256) {
        float s = bmean[c] + bmean[512 + c] + bmean[1024 + c];
        a += s * fc_w[d * 512 + c];
    }
    a = blockSum256(a, red);
    if (t == 0) fz[d] = a + fc_b[d];
}

// 2b) per-channel 3-way softmax
__global__ __launch_bounds__(128) void k_att2(
    const float* __restrict__ fz, const float* __restrict__ fcs_w,
    const float* __restrict__ fcs_b, float* __restrict__ att)
{
    __shared__ float sz[32];
    int t = threadIdx.x;
    int c = blockIdx.x * 128 + t;
    if (t < 32) sz[t] = fz[t];
    __syncthreads();
    float av[3];
    #pragma unroll
    for (int m = 0; m < 3; m++) {
        float a = fcs_b[m * 512 + c];
        const float* fw = fcs_w + (m * 512 + c) * 32;
        #pragma unroll
        for (int d = 0; d < 32; d++) a += sz[d] * fw[d];
        av[m] = a;
    }
    float mx = fmaxf(av[0], fmaxf(av[1], av[2]));
    float e0 = expf(av[0] - mx), e1 = expf(av[1] - mx), e2 = expf(av[2] - mx);
    float inv = 1.f / (e0 + e1 + e2);
    att[c] = e0 * inv; att[512 + c] = e1 * inv; att[1024 + c] = e2 * inv;
}

// 3) mix + downsample-transpose fused
__global__ __launch_bounds__(256) void k_mix_fd(const float* __restrict__ feas,
                                                const float* __restrict__ att,
                                                float* __restrict__ outres,
                                                float* __restrict__ fdT)
{
    int idx = blockIdx.x * 256 + threadIdx.x;
    int c = idx >> 10, o = idx & 1023;
    float v = att[c] * feas[idx] + att[512 + c] * feas[524288 + idx]
            + att[1024 + c] * feas[1048576 + idx];
    outres[idx] = v;
    int oy = o >> 5, ox = o & 31;
    if (!(oy & 1) && !(ox & 1)) {
        int s = (oy >> 1) * 16 + (ox >> 1);
        fdT[s * 512 + c] = v;
    }
}

// ---------------------------------------------------------------------------
// fp32 GEMM C = A * B^T (used only for the small gram matrix; exp-amplified
// path needs fp32 precision).
// ---------------------------------------------------------------------------
__global__ __launch_bounds__(256) void gemm_abt_f32(
    const float* __restrict__ A, const float* __restrict__ B,
    float* __restrict__ C, int M, int N, int K)
{
    __shared__ float As[16][68];
    __shared__ float Bs[16][68];
    int tid = threadIdx.x;
    int tx = tid & 15, ty = tid >> 4;
    int m0 = blockIdx.y * 64, n0 = blockIdx.x * 64;
    int a_m = tid >> 2, a_k4 = (tid & 3) * 4;
    float acc[4][4] = {};
    const float* aptr = A + (long)(m0 + a_m) * K + a_k4;
    const float* bptr = B + (long)(n0 + a_m) * K + a_k4;
    float4 av = *(const float4*)(aptr);
    float4 bv = *(const float4*)(bptr);
    for (int kt = 0; kt < K; kt += 16) {
        As[a_k4 + 0][a_m] = av.x; As[a_k4 + 1][a_m] = av.y;
        As[a_k4 + 2][a_m] = av.z; As[a_k4 + 3][a_m] = av.w;
        Bs[a_k4 + 0][a_m] = bv.x; Bs[a_k4 + 1][a_m] = bv.y;
        Bs[a_k4 + 2][a_m] = bv.z; Bs[a_k4 + 3][a_m] = bv.w;
        __syncthreads();
        if (kt + 16 < K) {
            av = *(const float4*)(aptr + kt + 16);
            bv = *(const float4*)(bptr + kt + 16);
        }
        #pragma unroll
        for (int kk = 0; kk < 16; kk++) {
            float4 a = *(const float4*)&As[kk][ty * 4];
            float4 b = *(const float4*)&Bs[kk][tx * 4];
            acc[0][0] += a.x * b.x; acc[0][1] += a.x * b.y; acc[0][2] += a.x * b.z; acc[0][3] += a.x * b.w;
            acc[1][0] += a.y * b.x; acc[1][1] += a.y * b.y; acc[1][2] += a.y * b.z; acc[1][3] += a.y * b.w;
            acc[2][0] += a.z * b.x; acc[2][1] += a.z * b.y; acc[2][2] += a.z * b.z; acc[2][3] += a.z * b.w;
            acc[3][0] += a.w * b.x; acc[3][1] += a.w * b.y; acc[3][2] += a.w * b.z; acc[3][3] += a.w * b.w;
        }
        __syncthreads();
    }
    #pragma unroll
    for (int i = 0; i < 4; i++) {
        float4 v = make_float4(acc[i][0], acc[i][1], acc[i][2], acc[i][3]);
        *(float4*)(C + (long)(m0 + ty * 4 + i) * N + n0 + tx * 4) = v;
    }
}

// ---------------------------------------------------------------------------
// tf32 tensor-core GEMMs. 64x64 block tile, BK=16, 8 warps (2x4),
// warp tile 32x16 = 2x2 m16n8k8 mma tiles. fp32 accumulate.
// ---------------------------------------------------------------------------
// C[m][n] = sum_k A[m][k] * B[k][n], B rows k<K1 from B1, else B2.
__global__ __launch_bounds__(256) void gemm_tf32_ab(
    const float* __restrict__ A, const float* __restrict__ B1,
    const float* __restrict__ B2, int K1, float* __restrict__ C,
    int M, int N, int K)
{
    __shared__ unsigned As[16][72];
    __shared__ unsigned Bs[16][72];
    int tid = threadIdx.x;
    int lane = tid & 31, wid = tid >> 5;
    int wm = (wid >> 2) * 32, wn = (wid & 3) * 16;
    int m0 = blockIdx.y * 64, n0 = blockIdx.x * 64;
    int a_m = tid >> 2, a_k4 = (tid & 3) * 4;
    int b_k = tid >> 4, b_n4 = (tid & 15) * 4;
    float cacc[2][2][4] = {};

    const float* aptr = A + (long)(m0 + a_m) * K + a_k4;
    float4 av = *(const float4*)(aptr);
    const float* bs0 = (b_k < K1) ? (B1 + (long)b_k * N) : (B2 + (long)(b_k - K1) * N);
    float4 bv = *(const float4*)(bs0 + n0 + b_n4);

    for (int kt = 0; kt < K; kt += 16) {
        As[a_k4 + 0][a_m] = cvt_tf32(av.x);
        As[a_k4 + 1][a_m] = cvt_tf32(av.y);
        As[a_k4 + 2][a_m] = cvt_tf32(av.z);
        As[a_k4 + 3][a_m] = cvt_tf32(av.w);
        Bs[b_k][b_n4 + 0] = cvt_tf32(bv.x);
        Bs[b_k][b_n4 + 1] = cvt_tf32(bv.y);
        Bs[b_k][b_n4 + 2] = cvt_tf32(bv.z);
        Bs[b_k][b_n4 + 3] = cvt_tf32(bv.w);
        __syncthreads();
        if (kt + 16 < K) {
            av = *(const float4*)(aptr + kt + 16);
            int gk = kt + 16 + b_k;
            const float* src = (gk < K1) ? (B1 + (long)gk * N) : (B2 + (long)(gk - K1) * N);
            bv = *(const float4*)(src + n0 + b_n4);
        }
        int r = lane >> 2, cl = lane & 3;
        #pragma unroll
        for (int ks = 0; ks < 16; ks += 8) {
            unsigned a[2][4], b[2][2];
            #pragma unroll
            for (int mt = 0; mt < 2; mt++) {
                int mb = wm + mt * 16 + r;
                a[mt][0] = As[ks + cl][mb];
                a[mt][1] = As[ks + cl][mb + 8];
                a[mt][2] = As[ks + cl + 4][mb];
                a[mt][3] = As[ks + cl + 4][mb + 8];
            }
            #pragma unroll
            for (int nt = 0; nt < 2; nt++) {
                int nb = wn + nt * 8 + r;
                b[nt][0] = Bs[ks + cl][nb];
                b[nt][1] = Bs[ks + cl + 4][nb];
            }
            #pragma unroll
            for (int mt = 0; mt < 2; mt++)
                #pragma unroll
                for (int nt = 0; nt < 2; nt++)
                    mma_tf32(cacc[mt][nt], a[mt], b[nt]);
        }
        __syncthreads();
    }
    int r = lane >> 2, cl = lane & 3;
    #pragma unroll
    for (int mt = 0; mt < 2; mt++) {
        #pragma unroll
        for (int nt = 0; nt < 2; nt++) {
            long row = m0 + wm + mt * 16 + r;
            long col = n0 + wn + nt * 8 + cl * 2;
            *(float2*)(C + row * N + col) =
                make_float2(cacc[mt][nt][0], cacc[mt][nt][1]);
            *(float2*)(C + (row + 8) * N + col) =
                make_float2(cacc[mt][nt][2], cacc[mt][nt][3]);
        }
    }
}

// C[m][n] = sum_k A[m][k] * B[n][k]
__global__ __launch_bounds__(256) void gemm_tf32_abt(
    const float* __restrict__ A, const float* __restrict__ B,
    float* __restrict__ C, int M, int N, int K)
{
    __shared__ unsigned As[16][72];
    __shared__ unsigned Bs[16][72];
    int tid = threadIdx.x;
    int lane = tid & 31, wid = tid >> 5;
    int wm = (wid >> 2) * 32, wn = (wid & 3) * 16;
    int m0 = blockIdx.y * 64, n0 = blockIdx.x * 64;
    int a_m = tid >> 2, a_k4 = (tid & 3) * 4;
    float cacc[2][2][4] = {};

    const float* aptr = A + (long)(m0 + a_m) * K + a_k4;
    const float* bptr = B + (long)(n0 + a_m) * K + a_k4;
    float4 av = *(const float4*)(aptr);
    float4 bv = *(const float4*)(bptr);

    for (int kt = 0; kt < K; kt += 16) {
        As[a_k4 + 0][a_m] = cvt_tf32(av.x);
        As[a_k4 + 1][a_m] = cvt_tf32(av.y);
        As[a_k4 + 2][a_m] = cvt_tf32(av.z);
        As[a_k4 + 3][a_m] = cvt_tf32(av.w);
        Bs[a_k4 + 0][a_m] = cvt_tf32(bv.x);
        Bs[a_k4 + 1][a_m] = cvt_tf32(bv.y);
        Bs[a_k4 + 2][a_m] = cvt_tf32(bv.z);
        Bs[a_k4 + 3][a_m] = cvt_tf32(bv.w);
        __syncthreads();
        if (kt + 16 < K) {
            av = *(const float4*)(aptr + kt + 16);
            bv = *(const float4*)(bptr + kt + 16);
        }
        int r = lane >> 2, cl = lane & 3;
        #pragma unroll
        for (int ks = 0; ks < 16; ks += 8) {
            unsigned a[2][4], b[2][2];
            #pragma unroll
            for (int mt = 0; mt < 2; mt++) {
                int mb = wm + mt * 16 + r;
                a[mt][0] = As[ks + cl][mb];
                a[mt][1] = As[ks + cl][mb + 8];
                a[mt][2] = As[ks + cl + 4][mb];
                a[mt][3] = As[ks + cl + 4][mb + 8];
            }
            #pragma unroll
            for (int nt = 0; nt < 2; nt++) {
                int nb = wn + nt * 8 + r;
                b[nt][0] = Bs[ks + cl][nb];
                b[nt][1] = Bs[ks + cl + 4][nb];
            }
            #pragma unroll
            for (int mt = 0; mt < 2; mt++)
                #pragma unroll
                for (int nt = 0; nt < 2; nt++)
                    mma_tf32(cacc[mt][nt], a[mt], b[nt]);
        }
        __syncthreads();
    }
    int r = lane >> 2, cl = lane & 3;
    #pragma unroll
    for (int mt = 0; mt < 2; mt++) {
        #pragma unroll
        for (int nt = 0; nt < 2; nt++) {
            long row = m0 + wm + mt * 16 + r;
            long col = n0 + wn + nt * 8 + cl * 2;
            *(float2*)(C + row * N + col) =
                make_float2(cacc[mt][nt][0], cacc[mt][nt][1]);
            *(float2*)(C + (row + 8) * N + col) =
                make_float2(cacc[mt][nt][2], cacc[mt][nt][3]);
        }
    }
}

// 6) yi from gram + col softmax
__global__ __launch_bounds__(256) void k_yis(const float* __restrict__ G,
                                             float* __restrict__ yis)
{
    __shared__ float red[9];
    int s = blockIdx.x, p = threadIdx.x;
    int sy = s >> 4, sx = s & 15;
    int py = p >> 4, px = p & 15;
    float raw = 0.f, nsum = 0.f;
    #pragma unroll
    for (int dy = -1; dy <= 1; dy++)
        #pragma unroll
        for (int dx = -1; dx <= 1; dx++) {
            int qy = py + dy, qx = px + dx;
            if (qy >= 0 && qy < 16 && qx >= 0 && qx < 16) {
                int q = qy * 16 + qx;
                nsum += G[q * 256 + q];
                int ry = sy + dy, rx = sx + dx;
                if (ry >= 0 && ry < 16 && rx >= 0 && rx < 16)
                    raw += G[q * 256 + ry * 16 + rx];
            }
        }
    float nrm = fmaxf(sqrtf(nsum), 1e-4f);
    float v = 10.f * raw / nrm;
    float mx = blockMax256(v, red);
    float e = expf(v - mx);
    float ssum = blockSum256(e, red);
    yis[p * 256 + s] = e / ssum;
}

// 7) build combined deconv matrix M[q][o] (replaces buildWk+batchGEMM+gather)
__global__ __launch_bounds__(256) void k_buildM(const float* __restrict__ yis,
                                                float* __restrict__ Mm)
{
    int idx = blockIdx.x * 256 + threadIdx.x;   // q*1024 + o
    int o = idx & 1023, q = idx >> 10;
    int oy = o >> 5, ox = o & 31;
    int qrow = q >> 5, qcol = q & 31;
    int kyv[2], syv[2], kxv[2], sxv[2];
    if (oy & 1) { kyv[0] = 1; syv[0] = (oy - 1) >> 1; kyv[1] = 3; syv[1] = (oy + 1) >> 1; }
    else        { kyv[0] = 0; syv[0] = (oy >> 1) - 1; kyv[1] = 2; syv[1] = oy >> 1; }
    if (ox & 1) { kxv[0] = 1; sxv[0] = (ox - 1) >> 1; kxv[1] = 3; sxv[1] = (ox + 1) >> 1; }
    else        { kxv[0] = 0; sxv[0] = (ox >> 1) - 1; kxv[1] = 2; sxv[1] = ox >> 1; }
    float acc = 0.f;
    #pragma unroll
    for (int a = 0; a < 2; a++) {
        if (syv[a] < 0 || syv[a] > 15) continue;
        int ty = qrow - 2 + kyv[a];
        if (ty < 0 || ty >= 32 || (ty & 1)) continue;
        int py = ty >> 1;
        #pragma unroll
        for (int b = 0; b < 2; b++) {
            if (sxv[b] < 0 || sxv[b] > 15) continue;
            int tx = qcol - 2 + kxv[b];
            if (tx < 0 || tx >= 32 || (tx & 1)) continue;
            int px = tx >> 1;
            acc += yis[(py * 16 + px) * 256 + syv[a] * 16 + sxv[b]];
        }
    }
    Mm[idx] = 0.25f * acc;
}

// 9) transpose [c][p] -> [p][c] + sigmoid copy
__global__ void k_transpose(const float* __restrict__ in,
                            float* __restrict__ outT, float* __restrict__ sigT)
{
    __shared__ float tile[32][33];
    int ps = blockIdx.x * 32, cs = blockIdx.y * 32;
    int tx = threadIdx.x, ty = threadIdx.y;
    #pragma unroll
    for (int r = 0; r < 4; r++)
        tile[ty + r * 8][tx] = in[(cs + ty + r * 8) * 1024 + ps + tx];
    __syncthreads();
    #pragma unroll
    for (int r = 0; r < 4; r++) {
        int p = ps + ty + r * 8;
        float v = tile[tx][ty + r * 8];
        outT[p * 512 + cs + tx] = v;
        sigT[p * 512 + cs + tx] = 1.f / (1.f + expf(-v));
    }
}

// 10) csa
__global__ __launch_bounds__(256) void k_csa(const float* __restrict__ sigT,
                                             const float* __restrict__ ralT,
                                             float* __restrict__ csab)
{
    __shared__ float ws[8][9];
    __shared__ float a9[9];
    int p = blockIdx.x, t = threadIdx.x;
    int lane = t & 31, w = t >> 5;
    int py = p >> 5, px = p & 31;
    int nb[9]; bool ok[9];
    #pragma unroll
    for (int d = 0; d < 9; d++) {
        int dy = d / 3 - 1, dx = d % 3 - 1;
        int y = py + dy, x = px + dx;
        ok[d] = (y >= 0 && y < 32 && x >= 0 && x < 32);
        nb[d] = ok[d] ? (y * 32 + x) : 0;
    }
    float loc[9] = {};
    for (int c = t; c < 512; c += 256) {
        float sv = sigT[p * 512 + c];
        #pragma unroll
        for (int d = 0; d < 9; d++)
            if (ok[d]) loc[d] += sv * sigT[nb[d] * 512 + c];
    }
    #pragma unroll
    for (int d = 0; d < 9; d++) {
        #pragma unroll
        for (int o = 16; o; o >>= 1) loc[d] += __shfl_down_sync(0xffffffffu, loc[d], o);
        if (lane == 0) ws[w][d] = loc[d];
    }
    __syncthreads();
    if (t < 9) {
        float s = 0.f;
        #pragma unroll
        for (int i = 0; i < 8; i++) s += ws[i][t];
        a9[t] = s * (1.f / 512.f);
    }
    __syncthreads();
    float mx = -1e30f;
    #pragma unroll
    for (int d = 0; d < 9; d++) mx = fmaxf(mx, a9[d]);
    float wgt[9]; float ssum = 0.f;
    #pragma unroll
    for (int d = 0; d < 9; d++) { wgt[d] = expf(a9[d] - mx); ssum += wgt[d]; }
    float inv = 1.f / ssum;
    for (int c = t; c < 512; c += 256) {
        float acc = 0.f;
        #pragma unroll
        for (int d = 0; d < 9; d++)
            if (ok[d]) acc += wgt[d] * ralT[nb[d] * 512 + c];
        csab[p * 512 + c] = acc * inv;
    }
}

// 11) instance norm + leaky relu 0.2
__global__ __launch_bounds__(256) void k_inorm_lrelu(const float* __restrict__ in,
                                                     float* __restrict__ out)
{
    __shared__ float red[9];
    int c = blockIdx.x, t = threadIdx.x;
    float v[4];
    #pragma unroll
    for (int q = 0; q < 4; q++) v[q] = in[c * 1024 + t + q * 256];
    float s  = v[0] + v[1] + v[2] + v[3];
    float sq = v[0]*v[0] + v[1]*v[1] + v[2]*v[2] + v[3]*v[3];
    s  = blockSum256(s,  red);
    sq = blockSum256(sq, red);
    float mean = s * (1.f / 1024.f);
    float var  = sq * (1.f / 1024.f) - mean * mean;
    float rstd = rsqrtf(var + 1e-5f);
    #pragma unroll
    for (int q = 0; q < 4; q++) {
        float z = (v[q] - mean) * rstd;
        out[c * 1024 + t + q * 256] = (z >= 0.f) ? z : 0.2f * z;
    }
}

// ---------------------------------------------------------------------------
extern "C" void kernel_launch(void* const* d_in, const int* in_sizes, int n_in,
                              void* d_out, int out_size)
{
    const float* x      = (const float*)d_in[0];
    const float* gus    = (const float*)d_in[1];
    const float* w3     = (const float*)d_in[2];
    const float* w5     = (const float*)d_in[4];
    const float* w7     = (const float*)d_in[6];
    const float* fc_w   = (const float*)d_in[8];
    const float* fc_b   = (const float*)d_in[9];
    const float* fcs_w  = (const float*)d_in[10];
    const float* fcs_b  = (const float*)d_in[11];
    const float* down_w = (const float*)d_in[12];
    const float* fuse_w = (const float*)d_in[13];
    float* out = (float*)d_out;

    void* sp = nullptr;
    cudaGetSymbolAddress(&sp, g_scratch);
    float* S = (float*)sp;
    float* feas   = S + O_FEAS;
    float* bmean  = S + O_BMEAN;
    float* att    = S + O_ATT;
    float* outres = S + O_OUTRES;
    float* fdT    = S + O_FDT;
    float* G      = S + O_G;
    float* fz     = S + O_FZ;
    float* yis    = S + O_YIS;
    float* Mm     = S + O_MM;
    float* ralout = S + O_RALOUT;
    float* ralT   = S + O_RALT;
    float* sigT   = S + O_SIGT;
    float* gusb   = S + O_GUSB;
    float* csab   = S + O_CSAB;
    float* y1raw  = S + O_Y1RAW;
    float* y1     = S + O_Y1;
    float* y2raw  = S + O_Y2RAW;

    static cudaStream_t s1 = nullptr, s2 = nullptr;
    static cudaEvent_t evA, ev1, ev2, evC, ev4;
    if (!s1) {
        cudaStreamCreateWithFlags(&s1, cudaStreamNonBlocking);
        cudaStreamCreateWithFlags(&s2, cudaStreamNonBlocking);
        cudaEventCreateWithFlags(&evA, cudaEventDisableTiming);
        cudaEventCreateWithFlags(&ev1, cudaEventDisableTiming);
        cudaEventCreateWithFlags(&ev2, cudaEventDisableTiming);
        cudaEventCreateWithFlags(&evC, cudaEventDisableTiming);
        cudaEventCreateWithFlags(&ev4, cudaEventDisableTiming);
    }

    // --- fork: 3 skconv branches concurrent ---
    cudaEventRecord(evA, 0);
    cudaStreamWaitEvent(s1, evA, 0);
    cudaStreamWaitEvent(s2, evA, 0);
    k_skconv<3><<<512, 256, (34 * 34 + 16 * 9)  * 4, 0 >>>(x, w3, feas,           bmean);
    k_skconv<5><<<512, 256, (36 * 36 + 16 * 25) * 4, s1>>>(x, w5, feas + 524288,  bmean + 512);
    k_skconv<7><<<512, 256, (38 * 38 + 16 * 49) * 4, s2>>>(x, w7, feas + 1048576, bmean + 1024);
    cudaEventRecord(ev1, s1);
    cudaEventRecord(ev2, s2);
    cudaStreamWaitEvent(0, ev1, 0);
    cudaStreamWaitEvent(0, ev2, 0);

    k_fcz <<<32, 256>>>(bmean, fc_w, fc_b, fz);
    k_att2<<<4, 128>>>(fz, fcs_w, fcs_b, att);
    k_mix_fd<<<2048, 256>>>(feas, att, outres, fdT);

    // gram (fp32 — feeds exp), yis, combined-deconv matrix M
    gemm_abt_f32<<<dim3(4, 4, 1), 256>>>(fdT, fdT, G, 256, 256, 512);
    k_yis<<<256, 256>>>(G, yis);
    k_buildM<<<4096, 256>>>(yis, Mm);
    // ral output as a single tf32 GEMM: ralout = outres (512x1024) * M (1024x1024)
    gemm_tf32_ab<<<dim3(16, 8, 1), 256>>>(outres, Mm, Mm, 1024, ralout,
                                          512, 1024, 1024);
    k_transpose<<<dim3(32, 16), dim3(32, 8)>>>(ralout, ralT, sigT);

    // --- fork: csa on s1, gus gemm on 0 ---
    cudaEventRecord(evC, 0);
    cudaStreamWaitEvent(s1, evC, 0);
    k_csa<<<1024, 256, 0, s1>>>(sigT, ralT, csab);
    gemm_tf32_abt<<<dim3(8, 16, 1), 256>>>(gus, ralout, gusb, 1024, 512, 1024);
    cudaEventRecord(ev4, s1);
    cudaStreamWaitEvent(0, ev4, 0);

    gemm_tf32_ab<<<dim3(16, 8, 1), 256>>>(down_w, gusb, csab, 512, y1raw,
                                          512, 1024, 1024);
    k_inorm_lrelu<<<512, 256>>>(y1raw, y1);
    gemm_tf32_ab<<<dim3(16, 8, 1), 256>>>(fuse_w, y1, outres, 512, y2raw,
                                          512, 1024, 1024);
    k_inorm_lrelu<<<512, 256>>>(y2raw, out);
}